// round 15
// baseline (speedup 1.0000x reference)
#include <cuda_runtime.h>
#include <cuda_fp16.h>

// Problem constants
#define B_ 4
#define H_ 192
#define W_ 640
#define C_ 32
#define S_ 32

#define Wp_   (W_ + 2)                 // padded width
#define ROWB  (Wp_ * 64)               // bytes per row in fp16 scratch (64B/pixel)
#define COPYB (B_ * H_ * ROWB)         // bytes per parity copy

// Two parity-shifted fp16 copies of x: for base column ib, one aligned 128B
// region holds [ x[ib] | x[ib+1] ].
#define COPY_CHUNKS (B_ * H_ * Wp_ * 4)
#define XS_CHUNKS   (2 * COPY_CHUNKS + Wp_ * 4)
__device__ uint4 d_xs[XS_CHUNKS];

// w-table: per (b,s,col,w): { byte-offset (incl. parity-copy base), weight fp32 }
struct __align__(8) WTab2 { int off; float w; };
__device__ WTab2 d_wt2[B_ * S_ * 2 * W_];
// h-table: per (b,s,h): { row0 byte base, row1 byte base, h0 fp32, h1 fp32 }
struct __align__(16) HTab { int r0, r1; float h0, h1; };
__device__ HTab d_ht[B_ * S_ * H_];

#define TAB_THREADS (B_ * S_ * (W_ + H_))
#define TAB_BLOCKS  ((TAB_THREADS + 255) / 256)
#define CONV_THREADS (B_ * H_ * Wp_ * 4)
#define CONV_BLOCKS  ((CONV_THREADS + 255) / 256)

// ---------------------------------------------------------------------------
// Fused prep kernel: table build + fp16 conversion (x read once).
// ---------------------------------------------------------------------------
__global__ void prep_kernel(const float4* __restrict__ x4,
                            const float* __restrict__ origin,
                            const float* __restrict__ focal,
                            const float* __restrict__ T12)
{
    if (blockIdx.x < TAB_BLOCKS) {
        int idx = blockIdx.x * blockDim.x + threadIdx.x;
        const int totalW = B_ * S_ * W_;
        const int totalH = B_ * S_ * H_;
        if (idx >= totalW + totalH) return;

        bool isW = idx < totalW;
        int rem  = isW ? idx : idx - totalW;
        int N    = isW ? W_ : H_;
        int pos  = rem % N;
        int s    = (rem / N) % S_;
        int b    = rem / (N * S_);

        float tz = T12[b * 3 + 2];
        float d  = (float)s;
        float D  = (s == 0) ? 0.0f : 1.0f / (1.0f / d + tz);
        float alpha = 1.0f - D * tz;

        float off;
        if (isW) off = D * tz * origin[b * 2 + 0] + D * focal[b * 2 + 0] * T12[b * 3 + 0];
        else     off = D * tz * origin[b * 2 + 1] + D * focal[b * 2 + 1] * T12[b * 3 + 1];

        float sp = alpha * (float)pos + off;
        float f0 = floorf(sp);
        float fr = sp - f0;
        int i0 = (int)f0;
        int i1 = i0 + 1;

        float w0 = (i0 >= 0 && i0 < N) ? (1.0f - fr) : 0.0f;
        float w1 = (i1 >= 0 && i1 < N) ? fr          : 0.0f;

        if (isW) {
            int ib; float wa, wb;
            if (i0 >= 0 && i0 < N)      { ib = i0; wa = w0; wb = w1; }
            else if (i0 == -1)          { ib = 0;  wa = w1; wb = 0.0f; }
            else                        { ib = min(max(i0, 0), N - 1); wa = 0.0f; wb = 0.0f; }
            int byteOff = (ib & 1) ? (COPYB + (ib + 1) * 64) : (ib * 64);
            int base = (b * S_ + s) * 2 * W_ + pos;
            WTab2 t0; t0.off = byteOff; t0.w = wa;
            WTab2 t1; t1.off = byteOff; t1.w = wb;
            d_wt2[base]      = t0;
            d_wt2[base + W_] = t1;
        } else {
            HTab t;
            int r0 = min(max(i0, 0), N - 1);
            int r1 = min(max(i1, 0), N - 1);
            t.r0 = (b * H_ + r0) * ROWB;
            t.r1 = (b * H_ + r1) * ROWB;
            t.h0 = w0;
            t.h1 = w1;
            d_ht[(b * S_ + s) * H_ + pos] = t;
        }
        return;
    }

    // --- conversion part ---
    int t = (blockIdx.x - TAB_BLOCKS) * blockDim.x + threadIdx.x;
    if (t >= CONV_THREADS) return;

    int c16  = t & 3;
    int rest = t >> 2;
    int wp   = rest % Wp_;  rest /= Wp_;
    int h    = rest % H_;
    int b    = rest / H_;

    uint4 o = make_uint4(0u, 0u, 0u, 0u);
    if (wp < W_) {
        const float4* src = x4 + ((((b * H_ + h) * W_ + wp) << 3) + (c16 << 1));
        float4 p = src[0];
        float4 q = src[1];
        __half2 a0 = __floats2half2_rn(p.x, p.y);
        __half2 a1 = __floats2half2_rn(p.z, p.w);
        __half2 a2 = __floats2half2_rn(q.x, q.y);
        __half2 a3 = __floats2half2_rn(q.z, q.w);
        o.x = *(unsigned int*)&a0;
        o.y = *(unsigned int*)&a1;
        o.z = *(unsigned int*)&a2;
        o.w = *(unsigned int*)&a3;
    }

    int rowChunk = (b * H_ + h) * Wp_ * 4;
    d_xs[rowChunk + wp * 4 + c16] = o;                                  // copy0[wp]
    if (wp + 1 < Wp_)
        d_xs[COPY_CHUNKS + rowChunk + (wp + 1) * 4 + c16] = o;          // copy1[wp+1] = x[wp]
    if (wp == 0)
        d_xs[COPY_CHUNKS + rowChunk + c16] = make_uint4(0u, 0u, 0u, 0u); // copy1[0] pad
    if (b == 0 && h == 0)
        d_xs[2 * COPY_CHUNKS + wp * 4 + c16] = make_uint4(0u, 0u, 0u, 0u); // final pad row
}

__device__ __forceinline__ __half2 u2h2_(unsigned int u)
{
    __half2 h; *(unsigned int*)&h = u; return h;
}

// One step's tap + dot (NO branch; per-LDG predication + zero-init only).
__device__ __forceinline__ float step_dot_nb(
    unsigned addr, unsigned m01u,
    const char* __restrict__ xsbL,
    const __half2* __restrict__ yh)
{
    uint4 A  = make_uint4(0u, 0u, 0u, 0u);
    uint4 Bv = make_uint4(0u, 0u, 0u, 0u);
    const char* pa = xsbL + (int)addr;
    if (m01u & 0x0000ffffu) A  = *(const uint4*)pa;
    if (m01u & 0xffff0000u) Bv = *(const uint4*)(pa + ROWB);

    __half2 dA = __hmul2(u2h2_(A.x), yh[0]);
    dA = __hfma2(u2h2_(A.y), yh[1], dA);
    dA = __hfma2(u2h2_(A.z), yh[2], dA);
    dA = __hfma2(u2h2_(A.w), yh[3], dA);

    __half2 dB = __hmul2(u2h2_(Bv.x), yh[0]);
    dB = __hfma2(u2h2_(Bv.y), yh[1], dB);
    dB = __hfma2(u2h2_(Bv.z), yh[2], dB);
    dB = __hfma2(u2h2_(Bv.w), yh[3], dB);

    __half2 m0h = u2h2_(__byte_perm(m01u, 0, 0x1010));
    __half2 m1h = u2h2_(__byte_perm(m01u, 0, 0x3232));
    __half2 dh  = __hfma2(m1h, dB, __hmul2(m0h, dA));

    float2 df = __half22float2(dh);
    return df.x + df.y;
}

// ---------------------------------------------------------------------------
// Main kernel = R14 (group-of-4 vote, branch-free active path), occupancy
// pushed 6 -> 7 blocks/SM (reg cap 36) to close the remaining ~13us
// latency-exposure gap (L1 binder at 90.5%, dur 141.4 vs L1-busy 128us).
// Spill signature to watch: L2% > 45 and dur regression -> revert to occ 6.
// ---------------------------------------------------------------------------
__global__ __launch_bounds__(256, 7) void corr_kernel(
    const float4* __restrict__ y4,
    float* __restrict__ out)
{
    const int tid  = threadIdx.x;
    const int wi   = tid >> 5;
    const int lane = tid & 31;
    const int sub  = lane >> 3;
    const int cg   = lane & 7;
    const int hiCol = (cg >> 2) & 1;

    int bx  = blockIdx.x;
    int twi = bx % (W_ / 8);
    int thi = (bx / (W_ / 8)) % (H_ / 4);
    int b   = bx / ((W_ / 8) * (H_ / 4));

    const int wl = (wi & 1) * 4 + sub;
    const int hl = wi >> 1;
    int w = twi * 8 + wl;
    int h = thi * 4 + hl;
    int p = (b * H_ + h) * W_ + w;

    // record table: idx = s*64 + hl*16 + wl*2 + col -> 2048 uint2 = 16 KB
    __shared__ uint2 srec[S_ * 4 * 8 * 2];

    // Build records: 8 per thread, coalesced STS.64.
#pragma unroll
    for (int k = 0; k < 8; ++k) {
        int r   = tid + k * 256;
        int col = r & 1;
        int wl2 = (r >> 1) & 7;
        int hl2 = (r >> 4) & 3;
        int s   = r >> 6;

        WTab2 wt = d_wt2[(b * S_ + s) * 2 * W_ + col * W_ + twi * 8 + wl2];
        HTab  ht = d_ht[(b * S_ + s) * H_ + thi * 4 + hl2];

        float m0 = ht.h0 * wt.w;
        float m1 = ht.h1 * wt.w;
        __half2 m01 = __floats2half2_rn(m0, m1);

        // If m0==0 (top border / OOB), anchor on r1 so base+ROWB = r1.
        int rbase = (m0 != 0.0f) ? ht.r0 : (ht.r1 - ROWB);

        uint2 rec;
        rec.x = (unsigned)(rbase + wt.off);
        rec.y = *(unsigned*)&m01;
        srec[r] = rec;
    }

    // y channels for this lane's group, pre-scaled by 1/C, converted to half2
    __half2 yh[4];
    {
        const float4* yp = y4 + (p << 3) + ((cg & 3) << 1);
        float4 a = yp[0], c = yp[1];
        const float sc = 1.0f / (float)C_;
        yh[0] = __floats2half2_rn(a.x * sc, a.y * sc);
        yh[1] = __floats2half2_rn(a.z * sc, a.w * sc);
        yh[2] = __floats2half2_rn(c.x * sc, c.y * sc);
        yh[3] = __floats2half2_rn(c.z * sc, c.w * sc);
    }

    __syncthreads();

    const char* xsbL = (const char*)d_xs + (cg << 4);
    const uint2* myrec = srec + (hl * 16 + wl * 2 + hiCol);
    float* outp = out + p * S_;

#pragma unroll 1
    for (int g = 0; g < S_ / 4; ++g) {
        // Load the group's 4 records up front (cheap broadcast LDS.64).
        uint2 r0 = myrec[(g * 4 + 0) * 64];
        uint2 r1 = myrec[(g * 4 + 1) * 64];
        uint2 r2 = myrec[(g * 4 + 2) * 64];
        uint2 r3 = myrec[(g * 4 + 3) * 64];

        float pr[4];
        // One vote per 4 steps: OOB-ness is monotone-ish in s, so groups are
        // almost always all-active or all-skip.
        if (__any_sync(0xffffffffu, (r0.y | r1.y | r2.y | r3.y) != 0u)) {
            pr[0] = step_dot_nb(r0.x, r0.y, xsbL, yh);
            pr[1] = step_dot_nb(r1.x, r1.y, xsbL, yh);
            pr[2] = step_dot_nb(r2.x, r2.y, xsbL, yh);
            pr[3] = step_dot_nb(r3.x, r3.y, xsbL, yh);
        } else {
            pr[0] = pr[1] = pr[2] = pr[3] = 0.0f;
        }

        // Butterfly: reduce 4 values over the 8 lanes of this pixel (fp32).
        float u = hiCol ? pr[0] : pr[2];
        float v = hiCol ? pr[1] : pr[3];
        u = __shfl_xor_sync(0xffffffffu, u, 4);
        v = __shfl_xor_sync(0xffffffffu, v, 4);
        float a  = hiCol ? (pr[2] + u) : (pr[0] + u);
        float bb = hiCol ? (pr[3] + v) : (pr[1] + v);
        bool hi2 = (cg & 2) != 0;
        float t = hi2 ? a : bb;
        t = __shfl_xor_sync(0xffffffffu, t, 2);
        float r = (hi2 ? bb : a) + t;
        r += __shfl_xor_sync(0xffffffffu, r, 1);

        if ((cg & 1) == 0) outp[g * 4 + (cg >> 1)] = r;
    }
}

// ---------------------------------------------------------------------------
extern "C" void kernel_launch(void* const* d_in, const int* in_sizes, int n_in,
                              void* d_out, int out_size)
{
    (void)in_sizes; (void)n_in; (void)out_size;
    const float* x      = (const float*)d_in[0];
    const float* y      = (const float*)d_in[1];
    const float* origin = (const float*)d_in[2];
    const float* focal  = (const float*)d_in[3];
    const float* T12    = (const float*)d_in[4];

    prep_kernel<<<TAB_BLOCKS + CONV_BLOCKS, 256>>>((const float4*)x, origin, focal, T12);

    int nBlocks = (W_ / 8) * (H_ / 4) * B_;   // 15360
    corr_kernel<<<nBlocks, 256>>>((const float4*)y, (float*)d_out);
}

// round 16
// speedup vs baseline: 1.0004x; 1.0004x over previous
#include <cuda_runtime.h>
#include <cuda_fp16.h>

// Problem constants
#define B_ 4
#define H_ 192
#define W_ 640
#define C_ 32
#define S_ 32

#define Wp_   (W_ + 2)                 // padded width
#define ROWB  (Wp_ * 64)               // bytes per row in fp16 scratch (64B/pixel)
#define COPYB (B_ * H_ * ROWB)         // bytes per parity copy

// Two parity-shifted fp16 copies of x: for base column ib, one aligned 128B
// region holds [ x[ib] | x[ib+1] ].
#define COPY_CHUNKS (B_ * H_ * Wp_ * 4)
#define XS_CHUNKS   (2 * COPY_CHUNKS + Wp_ * 4)
__device__ uint4 d_xs[XS_CHUNKS];

// w-table: per (b,s,col,w): { byte-offset (incl. parity-copy base), weight fp32 }
struct __align__(8) WTab2 { int off; float w; };
__device__ WTab2 d_wt2[B_ * S_ * 2 * W_];
// h-table: per (b,s,h): { row0 byte base, row1 byte base, h0 fp32, h1 fp32 }
struct __align__(16) HTab { int r0, r1; float h0, h1; };
__device__ HTab d_ht[B_ * S_ * H_];

#define TAB_THREADS (B_ * S_ * (W_ + H_))
#define TAB_BLOCKS  ((TAB_THREADS + 255) / 256)
#define CONV_THREADS (B_ * H_ * Wp_ * 4)
#define CONV_BLOCKS  ((CONV_THREADS + 255) / 256)

// ---------------------------------------------------------------------------
// Fused prep kernel: table build + fp16 conversion (x read once).
// ---------------------------------------------------------------------------
__global__ void prep_kernel(const float4* __restrict__ x4,
                            const float* __restrict__ origin,
                            const float* __restrict__ focal,
                            const float* __restrict__ T12)
{
    if (blockIdx.x < TAB_BLOCKS) {
        int idx = blockIdx.x * blockDim.x + threadIdx.x;
        const int totalW = B_ * S_ * W_;
        const int totalH = B_ * S_ * H_;
        if (idx >= totalW + totalH) return;

        bool isW = idx < totalW;
        int rem  = isW ? idx : idx - totalW;
        int N    = isW ? W_ : H_;
        int pos  = rem % N;
        int s    = (rem / N) % S_;
        int b    = rem / (N * S_);

        float tz = T12[b * 3 + 2];
        float d  = (float)s;
        float D  = (s == 0) ? 0.0f : 1.0f / (1.0f / d + tz);
        float alpha = 1.0f - D * tz;

        float off;
        if (isW) off = D * tz * origin[b * 2 + 0] + D * focal[b * 2 + 0] * T12[b * 3 + 0];
        else     off = D * tz * origin[b * 2 + 1] + D * focal[b * 2 + 1] * T12[b * 3 + 1];

        float sp = alpha * (float)pos + off;
        float f0 = floorf(sp);
        float fr = sp - f0;
        int i0 = (int)f0;
        int i1 = i0 + 1;

        float w0 = (i0 >= 0 && i0 < N) ? (1.0f - fr) : 0.0f;
        float w1 = (i1 >= 0 && i1 < N) ? fr          : 0.0f;

        if (isW) {
            int ib; float wa, wb;
            if (i0 >= 0 && i0 < N)      { ib = i0; wa = w0; wb = w1; }
            else if (i0 == -1)          { ib = 0;  wa = w1; wb = 0.0f; }
            else                        { ib = min(max(i0, 0), N - 1); wa = 0.0f; wb = 0.0f; }
            int byteOff = (ib & 1) ? (COPYB + (ib + 1) * 64) : (ib * 64);
            int base = (b * S_ + s) * 2 * W_ + pos;
            WTab2 t0; t0.off = byteOff; t0.w = wa;
            WTab2 t1; t1.off = byteOff; t1.w = wb;
            d_wt2[base]      = t0;
            d_wt2[base + W_] = t1;
        } else {
            HTab t;
            int r0 = min(max(i0, 0), N - 1);
            int r1 = min(max(i1, 0), N - 1);
            t.r0 = (b * H_ + r0) * ROWB;
            t.r1 = (b * H_ + r1) * ROWB;
            t.h0 = w0;
            t.h1 = w1;
            d_ht[(b * S_ + s) * H_ + pos] = t;
        }
        return;
    }

    // --- conversion part ---
    int t = (blockIdx.x - TAB_BLOCKS) * blockDim.x + threadIdx.x;
    if (t >= CONV_THREADS) return;

    int c16  = t & 3;
    int rest = t >> 2;
    int wp   = rest % Wp_;  rest /= Wp_;
    int h    = rest % H_;
    int b    = rest / H_;

    uint4 o = make_uint4(0u, 0u, 0u, 0u);
    if (wp < W_) {
        const float4* src = x4 + ((((b * H_ + h) * W_ + wp) << 3) + (c16 << 1));
        float4 p = src[0];
        float4 q = src[1];
        __half2 a0 = __floats2half2_rn(p.x, p.y);
        __half2 a1 = __floats2half2_rn(p.z, p.w);
        __half2 a2 = __floats2half2_rn(q.x, q.y);
        __half2 a3 = __floats2half2_rn(q.z, q.w);
        o.x = *(unsigned int*)&a0;
        o.y = *(unsigned int*)&a1;
        o.z = *(unsigned int*)&a2;
        o.w = *(unsigned int*)&a3;
    }

    int rowChunk = (b * H_ + h) * Wp_ * 4;
    d_xs[rowChunk + wp * 4 + c16] = o;                                  // copy0[wp]
    if (wp + 1 < Wp_)
        d_xs[COPY_CHUNKS + rowChunk + (wp + 1) * 4 + c16] = o;          // copy1[wp+1] = x[wp]
    if (wp == 0)
        d_xs[COPY_CHUNKS + rowChunk + c16] = make_uint4(0u, 0u, 0u, 0u); // copy1[0] pad
    if (b == 0 && h == 0)
        d_xs[2 * COPY_CHUNKS + wp * 4 + c16] = make_uint4(0u, 0u, 0u, 0u); // final pad row
}

__device__ __forceinline__ __half2 u2h2_(unsigned int u)
{
    __half2 h; *(unsigned int*)&h = u; return h;
}

// One step's tap + dot (NO branch; per-LDG predication + zero-init only).
__device__ __forceinline__ float step_dot_nb(
    unsigned addr, unsigned m01u,
    const char* __restrict__ xsbL,
    const __half2* __restrict__ yh)
{
    uint4 A  = make_uint4(0u, 0u, 0u, 0u);
    uint4 Bv = make_uint4(0u, 0u, 0u, 0u);
    const char* pa = xsbL + (int)addr;
    if (m01u & 0x0000ffffu) A  = *(const uint4*)pa;
    if (m01u & 0xffff0000u) Bv = *(const uint4*)(pa + ROWB);

    __half2 dA = __hmul2(u2h2_(A.x), yh[0]);
    dA = __hfma2(u2h2_(A.y), yh[1], dA);
    dA = __hfma2(u2h2_(A.z), yh[2], dA);
    dA = __hfma2(u2h2_(A.w), yh[3], dA);

    __half2 dB = __hmul2(u2h2_(Bv.x), yh[0]);
    dB = __hfma2(u2h2_(Bv.y), yh[1], dB);
    dB = __hfma2(u2h2_(Bv.z), yh[2], dB);
    dB = __hfma2(u2h2_(Bv.w), yh[3], dB);

    __half2 m0h = u2h2_(__byte_perm(m01u, 0, 0x1010));
    __half2 m1h = u2h2_(__byte_perm(m01u, 0, 0x3232));
    __half2 dh  = __hfma2(m1h, dB, __hmul2(m0h, dA));

    float2 df = __half22float2(dh);
    return df.x + df.y;
}

// ---------------------------------------------------------------------------
// Main kernel = R14 (occ 6, group-of-4 skip, branch-free active path) with
// the warp VOTE replaced by a PRECOMPUTED group-activity bitmask:
// builder thread's k-th record belongs to group g=k (s = (tid>>6) + 4k) and
// has constant hl = (tid>>4)&3, so it accumulates an 8-bit local mask for
// free; one atomicOr per thread into grpact[hl]. Main loop tests a register
// bit per group: skipped groups cost ~3 instrs and ZERO L1 (no record LDS,
// no vote). Mask is a conservative superset (ORs all 8 wl; warp spans 4) --
// extra-active groups run the correct predicated path -> bit-identical.
// ---------------------------------------------------------------------------
__global__ __launch_bounds__(256, 6) void corr_kernel(
    const float4* __restrict__ y4,
    float* __restrict__ out)
{
    const int tid  = threadIdx.x;
    const int wi   = tid >> 5;
    const int lane = tid & 31;
    const int sub  = lane >> 3;
    const int cg   = lane & 7;
    const int hiCol = (cg >> 2) & 1;

    int bx  = blockIdx.x;
    int twi = bx % (W_ / 8);
    int thi = (bx / (W_ / 8)) % (H_ / 4);
    int b   = bx / ((W_ / 8) * (H_ / 4));

    const int wl = (wi & 1) * 4 + sub;
    const int hl = wi >> 1;
    int w = twi * 8 + wl;
    int h = thi * 4 + hl;
    int p = (b * H_ + h) * W_ + w;

    // record table: idx = s*64 + hl*16 + wl*2 + col -> 2048 uint2 = 16 KB
    __shared__ uint2 srec[S_ * 4 * 8 * 2];
    __shared__ unsigned grpact[4];   // bit g = group g active for this hl

    if (tid < 4) grpact[tid] = 0u;

    // Build records: 8 per thread, coalesced STS.64. Accumulate activity.
    unsigned localmask = 0u;
#pragma unroll
    for (int k = 0; k < 8; ++k) {
        int r   = tid + k * 256;
        int col = r & 1;
        int wl2 = (r >> 1) & 7;
        int hl2 = (r >> 4) & 3;
        int s   = r >> 6;

        WTab2 wt = d_wt2[(b * S_ + s) * 2 * W_ + col * W_ + twi * 8 + wl2];
        HTab  ht = d_ht[(b * S_ + s) * H_ + thi * 4 + hl2];

        float m0 = ht.h0 * wt.w;
        float m1 = ht.h1 * wt.w;
        __half2 m01 = __floats2half2_rn(m0, m1);
        unsigned m01u = *(unsigned*)&m01;

        // If m0==0 (top border / OOB), anchor on r1 so base+ROWB = r1.
        int rbase = (m0 != 0.0f) ? ht.r0 : (ht.r1 - ROWB);

        uint2 rec;
        rec.x = (unsigned)(rbase + wt.off);
        rec.y = m01u;
        srec[r] = rec;

        if (m01u != 0u) localmask |= (1u << k);   // group g == k
    }

    // y channels for this lane's group, pre-scaled by 1/C, converted to half2
    __half2 yh[4];
    {
        const float4* yp = y4 + (p << 3) + ((cg & 3) << 1);
        float4 a = yp[0], c = yp[1];
        const float sc = 1.0f / (float)C_;
        yh[0] = __floats2half2_rn(a.x * sc, a.y * sc);
        yh[1] = __floats2half2_rn(a.z * sc, a.w * sc);
        yh[2] = __floats2half2_rn(c.x * sc, c.y * sc);
        yh[3] = __floats2half2_rn(c.z * sc, c.w * sc);
    }

    __syncthreads();                       // grpact init + records visible
    if (localmask)
        atomicOr(&grpact[(tid >> 4) & 3], localmask);
    __syncthreads();                       // grpact final

    const unsigned actmask = grpact[hl];

    const char* xsbL = (const char*)d_xs + (cg << 4);
    const uint2* myrec = srec + (hl * 16 + wl * 2 + hiCol);
    float* outp = out + p * S_;

#pragma unroll 1
    for (int g = 0; g < S_ / 4; ++g) {
        float pr[4];
        if ((actmask >> g) & 1u) {
            // Load the group's 4 records (cheap broadcast LDS.64).
            uint2 r0 = myrec[(g * 4 + 0) * 64];
            uint2 r1 = myrec[(g * 4 + 1) * 64];
            uint2 r2 = myrec[(g * 4 + 2) * 64];
            uint2 r3 = myrec[(g * 4 + 3) * 64];

            pr[0] = step_dot_nb(r0.x, r0.y, xsbL, yh);
            pr[1] = step_dot_nb(r1.x, r1.y, xsbL, yh);
            pr[2] = step_dot_nb(r2.x, r2.y, xsbL, yh);
            pr[3] = step_dot_nb(r3.x, r3.y, xsbL, yh);
        } else {
            pr[0] = pr[1] = pr[2] = pr[3] = 0.0f;
        }

        // Butterfly: reduce 4 values over the 8 lanes of this pixel (fp32).
        float u = hiCol ? pr[0] : pr[2];
        float v = hiCol ? pr[1] : pr[3];
        u = __shfl_xor_sync(0xffffffffu, u, 4);
        v = __shfl_xor_sync(0xffffffffu, v, 4);
        float a  = hiCol ? (pr[2] + u) : (pr[0] + u);
        float bb = hiCol ? (pr[3] + v) : (pr[1] + v);
        bool hi2 = (cg & 2) != 0;
        float t = hi2 ? a : bb;
        t = __shfl_xor_sync(0xffffffffu, t, 2);
        float r = (hi2 ? bb : a) + t;
        r += __shfl_xor_sync(0xffffffffu, r, 1);

        if ((cg & 1) == 0) outp[g * 4 + (cg >> 1)] = r;
    }
}

// ---------------------------------------------------------------------------
extern "C" void kernel_launch(void* const* d_in, const int* in_sizes, int n_in,
                              void* d_out, int out_size)
{
    (void)in_sizes; (void)n_in; (void)out_size;
    const float* x      = (const float*)d_in[0];
    const float* y      = (const float*)d_in[1];
    const float* origin = (const float*)d_in[2];
    const float* focal  = (const float*)d_in[3];
    const float* T12    = (const float*)d_in[4];

    prep_kernel<<<TAB_BLOCKS + CONV_BLOCKS, 256>>>((const float4*)x, origin, focal, T12);

    int nBlocks = (W_ / 8) * (H_ / 4) * B_;   // 15360
    corr_kernel<<<nBlocks, 256>>>((const float4*)y, (float*)d_out);
}

// round 17
// speedup vs baseline: 1.0822x; 1.0817x over previous
#include <cuda_runtime.h>
#include <cuda_fp16.h>

// Problem constants
#define B_ 4
#define H_ 192
#define W_ 640
#define C_ 32
#define S_ 32

#define Wp_   (W_ + 2)                 // padded width
#define ROWB  (Wp_ * 64)               // bytes per row in fp16 scratch (64B/pixel)
#define COPYB (B_ * H_ * ROWB)         // bytes per parity copy

// Two parity-shifted fp16 copies of x: for base column ib, one aligned 128B
// region holds [ x[ib] | x[ib+1] ].
#define COPY_CHUNKS (B_ * H_ * Wp_ * 4)
#define XS_CHUNKS   (2 * COPY_CHUNKS + Wp_ * 4)
__device__ uint4 d_xs[XS_CHUNKS];

// w-table: per (b,s,col,w): { byte-offset (incl. parity-copy base), weight fp32 }
struct __align__(8) WTab2 { int off; float w; };
__device__ WTab2 d_wt2[B_ * S_ * 2 * W_];
// h-table: per (b,s,h): { row0 byte base, row1 byte base, h0 fp32, h1 fp32 }
struct __align__(16) HTab { int r0, r1; float h0, h1; };
__device__ HTab d_ht[B_ * S_ * H_];

#define TAB_THREADS (B_ * S_ * (W_ + H_))
#define TAB_BLOCKS  ((TAB_THREADS + 255) / 256)
#define CONV_THREADS (B_ * H_ * Wp_ * 4)
#define CONV_BLOCKS  ((CONV_THREADS + 255) / 256)

// ---------------------------------------------------------------------------
// Fused prep kernel: table build + fp16 conversion (x read once, streaming).
// d_xs writes use DEFAULT policy so the 63MB fp16 scratch stays L2-resident
// (L2 is ~126MB); all single-use streams are tagged streaming.
// ---------------------------------------------------------------------------
__global__ void prep_kernel(const float4* __restrict__ x4,
                            const float* __restrict__ origin,
                            const float* __restrict__ focal,
                            const float* __restrict__ T12)
{
    if (blockIdx.x < TAB_BLOCKS) {
        int idx = blockIdx.x * blockDim.x + threadIdx.x;
        const int totalW = B_ * S_ * W_;
        const int totalH = B_ * S_ * H_;
        if (idx >= totalW + totalH) return;

        bool isW = idx < totalW;
        int rem  = isW ? idx : idx - totalW;
        int N    = isW ? W_ : H_;
        int pos  = rem % N;
        int s    = (rem / N) % S_;
        int b    = rem / (N * S_);

        float tz = T12[b * 3 + 2];
        float d  = (float)s;
        float D  = (s == 0) ? 0.0f : 1.0f / (1.0f / d + tz);
        float alpha = 1.0f - D * tz;

        float off;
        if (isW) off = D * tz * origin[b * 2 + 0] + D * focal[b * 2 + 0] * T12[b * 3 + 0];
        else     off = D * tz * origin[b * 2 + 1] + D * focal[b * 2 + 1] * T12[b * 3 + 1];

        float sp = alpha * (float)pos + off;
        float f0 = floorf(sp);
        float fr = sp - f0;
        int i0 = (int)f0;
        int i1 = i0 + 1;

        float w0 = (i0 >= 0 && i0 < N) ? (1.0f - fr) : 0.0f;
        float w1 = (i1 >= 0 && i1 < N) ? fr          : 0.0f;

        if (isW) {
            int ib; float wa, wb;
            if (i0 >= 0 && i0 < N)      { ib = i0; wa = w0; wb = w1; }
            else if (i0 == -1)          { ib = 0;  wa = w1; wb = 0.0f; }
            else                        { ib = min(max(i0, 0), N - 1); wa = 0.0f; wb = 0.0f; }
            int byteOff = (ib & 1) ? (COPYB + (ib + 1) * 64) : (ib * 64);
            int base = (b * S_ + s) * 2 * W_ + pos;
            WTab2 t0; t0.off = byteOff; t0.w = wa;
            WTab2 t1; t1.off = byteOff; t1.w = wb;
            d_wt2[base]      = t0;
            d_wt2[base + W_] = t1;
        } else {
            HTab t;
            int r0 = min(max(i0, 0), N - 1);
            int r1 = min(max(i1, 0), N - 1);
            t.r0 = (b * H_ + r0) * ROWB;
            t.r1 = (b * H_ + r1) * ROWB;
            t.h0 = w0;
            t.h1 = w1;
            d_ht[(b * S_ + s) * H_ + pos] = t;
        }
        return;
    }

    // --- conversion part ---
    int t = (blockIdx.x - TAB_BLOCKS) * blockDim.x + threadIdx.x;
    if (t >= CONV_THREADS) return;

    int c16  = t & 3;
    int rest = t >> 2;
    int wp   = rest % Wp_;  rest /= Wp_;
    int h    = rest % H_;
    int b    = rest / H_;

    uint4 o = make_uint4(0u, 0u, 0u, 0u);
    if (wp < W_) {
        const float4* src = x4 + ((((b * H_ + h) * W_ + wp) << 3) + (c16 << 1));
        float4 p = __ldcs(src);          // x fp32: read exactly once -> stream
        float4 q = __ldcs(src + 1);
        __half2 a0 = __floats2half2_rn(p.x, p.y);
        __half2 a1 = __floats2half2_rn(p.z, p.w);
        __half2 a2 = __floats2half2_rn(q.x, q.y);
        __half2 a3 = __floats2half2_rn(q.z, q.w);
        o.x = *(unsigned int*)&a0;
        o.y = *(unsigned int*)&a1;
        o.z = *(unsigned int*)&a2;
        o.w = *(unsigned int*)&a3;
    }

    int rowChunk = (b * H_ + h) * Wp_ * 4;
    d_xs[rowChunk + wp * 4 + c16] = o;                                  // copy0[wp]
    if (wp + 1 < Wp_)
        d_xs[COPY_CHUNKS + rowChunk + (wp + 1) * 4 + c16] = o;          // copy1[wp+1] = x[wp]
    if (wp == 0)
        d_xs[COPY_CHUNKS + rowChunk + c16] = make_uint4(0u, 0u, 0u, 0u); // copy1[0] pad
    if (b == 0 && h == 0)
        d_xs[2 * COPY_CHUNKS + wp * 4 + c16] = make_uint4(0u, 0u, 0u, 0u); // final pad row
}

__device__ __forceinline__ __half2 u2h2_(unsigned int u)
{
    __half2 h; *(unsigned int*)&h = u; return h;
}

// One step's tap + dot (NO branch; per-LDG predication + zero-init only).
__device__ __forceinline__ float step_dot_nb(
    unsigned addr, unsigned m01u,
    const char* __restrict__ xsbL,
    const __half2* __restrict__ yh)
{
    uint4 A  = make_uint4(0u, 0u, 0u, 0u);
    uint4 Bv = make_uint4(0u, 0u, 0u, 0u);
    const char* pa = xsbL + (int)addr;
    if (m01u & 0x0000ffffu) A  = *(const uint4*)pa;
    if (m01u & 0xffff0000u) Bv = *(const uint4*)(pa + ROWB);

    __half2 dA = __hmul2(u2h2_(A.x), yh[0]);
    dA = __hfma2(u2h2_(A.y), yh[1], dA);
    dA = __hfma2(u2h2_(A.z), yh[2], dA);
    dA = __hfma2(u2h2_(A.w), yh[3], dA);

    __half2 dB = __hmul2(u2h2_(Bv.x), yh[0]);
    dB = __hfma2(u2h2_(Bv.y), yh[1], dB);
    dB = __hfma2(u2h2_(Bv.z), yh[2], dB);
    dB = __hfma2(u2h2_(Bv.w), yh[3], dB);

    __half2 m0h = u2h2_(__byte_perm(m01u, 0, 0x1010));
    __half2 m1h = u2h2_(__byte_perm(m01u, 0, 0x3232));
    __half2 dh  = __hfma2(m1h, dB, __hmul2(m0h, dA));

    float2 df = __half22float2(dh);
    return df.x + df.y;
}

// ---------------------------------------------------------------------------
// Main kernel = EXACT R14 structure (best: 141.4us main): occ 6, group-of-4
// warp vote, branch-free predicated active path. Only change vs R14:
// streaming cache hints on single-use traffic (y reads via __ldcs, output
// stores via __stcs) so the 63MB fp16 x-scratch keeps L2 residency ->
// tap misses resolve at L2 (~234cyc) instead of DRAM (~577cyc).
// ---------------------------------------------------------------------------
__global__ __launch_bounds__(256, 6) void corr_kernel(
    const float4* __restrict__ y4,
    float* __restrict__ out)
{
    const int tid  = threadIdx.x;
    const int wi   = tid >> 5;
    const int lane = tid & 31;
    const int sub  = lane >> 3;
    const int cg   = lane & 7;
    const int hiCol = (cg >> 2) & 1;

    int bx  = blockIdx.x;
    int twi = bx % (W_ / 8);
    int thi = (bx / (W_ / 8)) % (H_ / 4);
    int b   = bx / ((W_ / 8) * (H_ / 4));

    const int wl = (wi & 1) * 4 + sub;
    const int hl = wi >> 1;
    int w = twi * 8 + wl;
    int h = thi * 4 + hl;
    int p = (b * H_ + h) * W_ + w;

    // record table: idx = s*64 + hl*16 + wl*2 + col -> 2048 uint2 = 16 KB
    __shared__ uint2 srec[S_ * 4 * 8 * 2];

    // Build records: 8 per thread, coalesced STS.64.
#pragma unroll
    for (int k = 0; k < 8; ++k) {
        int r   = tid + k * 256;
        int col = r & 1;
        int wl2 = (r >> 1) & 7;
        int hl2 = (r >> 4) & 3;
        int s   = r >> 6;

        WTab2 wt = d_wt2[(b * S_ + s) * 2 * W_ + col * W_ + twi * 8 + wl2];
        HTab  ht = d_ht[(b * S_ + s) * H_ + thi * 4 + hl2];

        float m0 = ht.h0 * wt.w;
        float m1 = ht.h1 * wt.w;
        __half2 m01 = __floats2half2_rn(m0, m1);

        // If m0==0 (top border / OOB), anchor on r1 so base+ROWB = r1.
        int rbase = (m0 != 0.0f) ? ht.r0 : (ht.r1 - ROWB);

        uint2 rec;
        rec.x = (unsigned)(rbase + wt.off);
        rec.y = *(unsigned*)&m01;
        srec[r] = rec;
    }

    // y channels (read exactly once -> streaming), pre-scaled by 1/C, half2
    __half2 yh[4];
    {
        const float4* yp = y4 + (p << 3) + ((cg & 3) << 1);
        float4 a = __ldcs(yp);
        float4 c = __ldcs(yp + 1);
        const float sc = 1.0f / (float)C_;
        yh[0] = __floats2half2_rn(a.x * sc, a.y * sc);
        yh[1] = __floats2half2_rn(a.z * sc, a.w * sc);
        yh[2] = __floats2half2_rn(c.x * sc, c.y * sc);
        yh[3] = __floats2half2_rn(c.z * sc, c.w * sc);
    }

    __syncthreads();

    const char* xsbL = (const char*)d_xs + (cg << 4);
    const uint2* myrec = srec + (hl * 16 + wl * 2 + hiCol);
    float* outp = out + p * S_;

#pragma unroll 1
    for (int g = 0; g < S_ / 4; ++g) {
        // Load the group's 4 records up front (cheap broadcast LDS.64).
        uint2 r0 = myrec[(g * 4 + 0) * 64];
        uint2 r1 = myrec[(g * 4 + 1) * 64];
        uint2 r2 = myrec[(g * 4 + 2) * 64];
        uint2 r3 = myrec[(g * 4 + 3) * 64];

        float pr[4];
        // One vote per 4 steps: OOB-ness is monotone-ish in s, so groups are
        // almost always all-active or all-skip.
        if (__any_sync(0xffffffffu, (r0.y | r1.y | r2.y | r3.y) != 0u)) {
            pr[0] = step_dot_nb(r0.x, r0.y, xsbL, yh);
            pr[1] = step_dot_nb(r1.x, r1.y, xsbL, yh);
            pr[2] = step_dot_nb(r2.x, r2.y, xsbL, yh);
            pr[3] = step_dot_nb(r3.x, r3.y, xsbL, yh);
        } else {
            pr[0] = pr[1] = pr[2] = pr[3] = 0.0f;
        }

        // Butterfly: reduce 4 values over the 8 lanes of this pixel (fp32).
        float u = hiCol ? pr[0] : pr[2];
        float v = hiCol ? pr[1] : pr[3];
        u = __shfl_xor_sync(0xffffffffu, u, 4);
        v = __shfl_xor_sync(0xffffffffu, v, 4);
        float a  = hiCol ? (pr[2] + u) : (pr[0] + u);
        float bb = hiCol ? (pr[3] + v) : (pr[1] + v);
        bool hi2 = (cg & 2) != 0;
        float t = hi2 ? a : bb;
        t = __shfl_xor_sync(0xffffffffu, t, 2);
        float r = (hi2 ? bb : a) + t;
        r += __shfl_xor_sync(0xffffffffu, r, 1);

        if ((cg & 1) == 0) __stcs(&outp[g * 4 + (cg >> 1)], r);  // written once
    }
}

// ---------------------------------------------------------------------------
extern "C" void kernel_launch(void* const* d_in, const int* in_sizes, int n_in,
                              void* d_out, int out_size)
{
    (void)in_sizes; (void)n_in; (void)out_size;
    const float* x      = (const float*)d_in[0];
    const float* y      = (const float*)d_in[1];
    const float* origin = (const float*)d_in[2];
    const float* focal  = (const float*)d_in[3];
    const float* T12    = (const float*)d_in[4];

    prep_kernel<<<TAB_BLOCKS + CONV_BLOCKS, 256>>>((const float4*)x, origin, focal, T12);

    int nBlocks = (W_ / 8) * (H_ / 4) * B_;   // 15360
    corr_kernel<<<nBlocks, 256>>>((const float4*)y, (float*)d_out);
}